// round 13
// baseline (speedup 1.0000x reference)
#include <cuda_runtime.h>
#include <cuda_bf16.h>
#include <math.h>

#define NN 50000
#define NE 800000
#define D1 128
#define D2 32

// ---------------- scratch (device globals; no allocations) ----------------
__device__ __align__(16) float g_Wh2[(size_t)NN * D2];
__device__ __align__(16) float g_xg[(size_t)NE * 8];  // premultiplied w*x rows
__device__ float g_w1[NE];           // layer-1 edge weights (CSR order)
__device__ float g_es2[NN], g_ed2[NN];
__device__ float g_ed1n[NN];         // x[n] . c2
__device__ int   g_deg[NN];          // histogram, then scatter cursor
__device__ int   g_rowstart[NN + 1];
__device__ int   g_csrc[NE];         // CSR: src node per slot (dst-sorted)
__device__ int   g_cdst[NE];         // CSR: dst node per slot
__device__ float g_c1[8], g_c2[8];   // W1 @ a1[:D1], W1 @ a1[D1:]

// ================= c1 = W1 @ a1[:D1], c2 = W1 @ a1[D1:] ===================
__global__ void k_c12(const float* __restrict__ W1,
                      const float* __restrict__ a1) {
    int w = threadIdx.x >> 5, lane = threadIdx.x & 31;  // 16 warps
    int k = w & 7;
    const float* av = a1 + ((w < 8) ? 0 : D1);
    float p = 0.f;
    for (int j = lane; j < D1; j += 32) p += W1[k * D1 + j] * av[j];
#pragma unroll
    for (int o = 16; o; o >>= 1) p += __shfl_xor_sync(0xffffffffu, p, o);
    if (lane == 0) {
        if (w < 8) g_c1[k] = p; else g_c2[k] = p;
    }
}

// ====== per-node pre-pass: zero deg + ed1n = x . c2 (after k_c12) =========
__global__ void k_pre(const float* __restrict__ x) {
    int i = blockIdx.x * blockDim.x + threadIdx.x;
    if (i >= NN) return;
    g_deg[i] = 0;
    const float4* xn = reinterpret_cast<const float4*>(x + (size_t)i * 8);
    float4 lo = xn[0], hi = xn[1];
    g_ed1n[i] = lo.x * g_c2[0] + lo.y * g_c2[1] + lo.z * g_c2[2] + lo.w * g_c2[3]
              + hi.x * g_c2[4] + hi.y * g_c2[5] + hi.z * g_c2[6] + hi.w * g_c2[7];
}

__global__ void k_hist(const int* __restrict__ dst) {
    int e = blockIdx.x * blockDim.x + threadIdx.x;
    if (e < NE) atomicAdd(&g_deg[dst[e]], 1);
}

// single-block exclusive scan of g_deg -> g_rowstart; re-zeroes g_deg (cursor)
__global__ void k_scan() {
    const int T = 1024;
    const int CH = (NN + T - 1) / T;  // 49
    int t = threadIdx.x;
    int base = t * CH;

    int s = 0;
    for (int i = 0; i < CH; i++) {
        int idx = base + i;
        if (idx < NN) s += g_deg[idx];
    }
    __shared__ int warpsum[32];
    int lane = t & 31, w = t >> 5;
    int incl = s;
#pragma unroll
    for (int o = 1; o < 32; o <<= 1) {
        int v = __shfl_up_sync(0xffffffffu, incl, o);
        if (lane >= o) incl += v;
    }
    if (lane == 31) warpsum[w] = incl;
    __syncthreads();
    if (w == 0) {
        int v = warpsum[lane];
#pragma unroll
        for (int o = 1; o < 32; o <<= 1) {
            int u = __shfl_up_sync(0xffffffffu, v, o);
            if (lane >= o) v += u;
        }
        warpsum[lane] = v;
    }
    __syncthreads();
    int excl = incl - s + ((w > 0) ? warpsum[w - 1] : 0);

    int run = excl;
    for (int i = 0; i < CH; i++) {
        int idx = base + i;
        if (idx < NN) {
            g_rowstart[idx] = run;
            run += g_deg[idx];
            g_deg[idx] = 0;  // becomes scatter cursor
        }
    }
    if (t == T - 1) g_rowstart[NN] = run;
}

__global__ void k_scatter(const int* __restrict__ src,
                          const int* __restrict__ dst) {
    int e = blockIdx.x * blockDim.x + threadIdx.x;
    if (e >= NE) return;
    int d = dst[e];
    int pos = g_rowstart[d] + atomicAdd(&g_deg[d], 1);
    g_csrc[pos] = src[e];
    g_cdst[pos] = d;
}

// edge weight: exp(leaky_relu(logit)). Global max-shift dropped: it enters
// only through the +1e-9 denominator term (rel effect ~1e-10 here).
__device__ __forceinline__ float edge_w(float lg) {
    float v = (lg > 0.f) ? lg : 0.2f * lg;
    return __expf(v);
}

// ===== permute + full layer-1 edge math: xg[i] = w_i * x[csrc[i]] =========
__global__ void k_permx(const float* __restrict__ x) {
    int i = blockIdx.x * blockDim.x + threadIdx.x;
    if (i >= NE) return;
    int s = g_csrc[i];
    int d = g_cdst[i];
    const float4* xs = reinterpret_cast<const float4*>(x + (size_t)s * 8);
    float4 lo = xs[0], hi = xs[1];
    float es = lo.x * g_c1[0] + lo.y * g_c1[1] + lo.z * g_c1[2] + lo.w * g_c1[3]
             + hi.x * g_c1[4] + hi.y * g_c1[5] + hi.z * g_c1[6] + hi.w * g_c1[7];
    float w = edge_w(es + g_ed1n[d]);
    g_w1[i] = w;
    lo.x *= w; lo.y *= w; lo.z *= w; lo.w *= w;
    hi.x *= w; hi.y *= w; hi.z *= w; hi.w *= w;
    float4* o = reinterpret_cast<float4*>(g_xg) + (size_t)i * 2;
    o[0] = lo; o[1] = hi;
}

// ===== fused layer1: pure streaming sum + @W1 + elu + node2 matvec ========
__global__ void k_gagg1_node2(const float* __restrict__ W1,
                              const float* __restrict__ W2,
                              const float* __restrict__ a2) {
    __shared__ float sW1[8 * D1];    // 4 KB
    __shared__ float sW2[D1 * D2];   // 16 KB
    __shared__ float sa[2 * D2];
    __shared__ float sh[16][D1];     // per-warp out1 row (16 warps)
    int tid = threadIdx.x;
    for (int i = tid; i < 8 * D1; i += blockDim.x) sW1[i] = W1[i];
    for (int i = tid; i < D1 * D2; i += blockDim.x) sW2[i] = W2[i];
    for (int i = tid; i < 2 * D2; i += blockDim.x) sa[i] = a2[i];
    __syncthreads();

    int warp = tid >> 5, lane = tid & 31;
    int node = blockIdx.x * (blockDim.x >> 5) + warp;
    if (node >= NN) return;

    int beg = g_rowstart[node], end = g_rowstart[node + 1];
    int half = lane & 1;  // lane pair per edge: even=comps 0-3, odd=4-7

    // streaming sum of premultiplied rows (16 edges / 512B per pass)
    float a0 = 0.f, a1r = 0.f, a2r = 0.f, a3 = 0.f;
    for (int idx = beg + (lane >> 1); idx < end; idx += 16) {
        float4 v = reinterpret_cast<const float4*>(g_xg)[(size_t)idx * 2 + half];
        a0 += v.x; a1r += v.y; a2r += v.z; a3 += v.w;
    }
    // streaming weight sum (coalesced, all 32 lanes)
    float psum = 0.f;
    for (int i = beg + lane; i < end; i += 32) psum += g_w1[i];

    // reduce over lane pairs; even lanes hold comps 0-3, odd hold 4-7
#pragma unroll
    for (int o = 2; o <= 16; o <<= 1) {
        a0  += __shfl_xor_sync(0xffffffffu, a0,  o);
        a1r += __shfl_xor_sync(0xffffffffu, a1r, o);
        a2r += __shfl_xor_sync(0xffffffffu, a2r, o);
        a3  += __shfl_xor_sync(0xffffffffu, a3,  o);
    }
#pragma unroll
    for (int o = 16; o; o >>= 1) psum += __shfl_xor_sync(0xffffffffu, psum, o);

    // exchange halves so every lane holds the full aggx[8]
    float t0 = __shfl_xor_sync(0xffffffffu, a0,  1);
    float t1 = __shfl_xor_sync(0xffffffffu, a1r, 1);
    float t2 = __shfl_xor_sync(0xffffffffu, a2r, 1);
    float t3 = __shfl_xor_sync(0xffffffffu, a3,  1);
    float b0 = half ? t0 : a0,  b4 = half ? a0  : t0;
    float b1 = half ? t1 : a1r, b5 = half ? a1r : t1;
    float b2 = half ? t2 : a2r, b6 = half ? a2r : t2;
    float b3 = half ? t3 : a3,  b7 = half ? a3  : t3;

    float inv = 1.f / (psum + 1e-9f);
    // out1[j] = elu( inv * (aggx @ W1)[j] )
#pragma unroll
    for (int i = 0; i < 4; i++) {
        int j = i * 32 + lane;
        float o = b0 * sW1[0 * D1 + j] + b1 * sW1[1 * D1 + j]
                + b2 * sW1[2 * D1 + j] + b3 * sW1[3 * D1 + j]
                + b4 * sW1[4 * D1 + j] + b5 * sW1[5 * D1 + j]
                + b6 * sW1[6 * D1 + j] + b7 * sW1[7 * D1 + j];
        o *= inv;
        o = (o > 0.f) ? o : expm1f(o);  // elu fused
        sh[warp][j] = o;
    }
    __syncwarp();

    // node2: Wh2 = out1 @ W2, es2/ed2
    int j = lane;
    float acc = 0.f;
#pragma unroll 8
    for (int k = 0; k < D1; k++) acc += sh[warp][k] * sW2[k * D2 + j];

    g_Wh2[(size_t)node * D2 + j] = acc;

    float es = acc * sa[j];
    float ed = acc * sa[D2 + j];
#pragma unroll
    for (int o = 16; o; o >>= 1) {
        es += __shfl_down_sync(0xffffffffu, es, o);
        ed += __shfl_down_sync(0xffffffffu, ed, o);
    }
    if (lane == 0) {
        g_es2[node] = es;
        g_ed2[node] = ed;
    }
}

// ====== fused: chunked gather layer2 (D=32) + elu + MLP head ==============
__global__ void k_gagg2_head(const float* __restrict__ hw1,
                             const float* __restrict__ hb1,
                             const float* __restrict__ hw2,
                             const float* __restrict__ hb2,
                             float* __restrict__ out) {
    __shared__ float sw1[32 * 32];
    __shared__ float sb1[32];
    __shared__ float sw2[32];
    __shared__ float sh[8][32];
    int tid = threadIdx.x;
    for (int i = tid; i < 32 * 32; i += blockDim.x) sw1[i] = hw1[i];
    if (tid < 32) { sb1[tid] = hb1[tid]; sw2[tid] = hw2[tid]; }
    __syncthreads();

    int warp = tid >> 5, lane = tid & 31;
    int node = blockIdx.x * (blockDim.x >> 5) + warp;
    if (node >= NN) return;

    int beg = g_rowstart[node], end = g_rowstart[node + 1];
    float edc = g_ed2[node];

    float acc = 0.f, psum = 0.f;
    for (int base = beg; base < end; base += 32) {
        int cnt = min(32, end - base);
        int   s = 0;
        float w = 0.f;
        if (lane < cnt) {
            s = g_csrc[base + lane];
            w = edge_w(g_es2[s] + edc);
        }
        psum += w;
        if (cnt == 32) {
#pragma unroll 8
            for (int j = 0; j < 32; j++) {
                int   sj = __shfl_sync(0xffffffffu, s, j);
                float wj = __shfl_sync(0xffffffffu, w, j);
                acc += wj * g_Wh2[(size_t)sj * D2 + lane];
            }
        } else {
            for (int j = 0; j < cnt; j++) {
                int   sj = __shfl_sync(0xffffffffu, s, j);
                float wj = __shfl_sync(0xffffffffu, w, j);
                acc += wj * g_Wh2[(size_t)sj * D2 + lane];
            }
        }
    }
    float asum = psum;
#pragma unroll
    for (int o = 16; o; o >>= 1) asum += __shfl_xor_sync(0xffffffffu, asum, o);

    acc *= 1.f / (asum + 1e-9f);
    float h = (acc > 0.f) ? acc : expm1f(acc);   // elu fused

    sh[warp][lane] = h;
    __syncwarp();

    float z = sb1[lane];
#pragma unroll 8
    for (int k = 0; k < 32; k++) z += sh[warp][k] * sw1[k * 32 + lane];

    // exact gelu: 0.5*x*(1+erf(x/sqrt(2)))
    float g = 0.5f * z * (1.f + erff(z * 0.70710678118654752f));
    float sc = g * sw2[lane];
#pragma unroll
    for (int o = 16; o; o >>= 1) sc += __shfl_down_sync(0xffffffffu, sc, o);
    if (lane == 0) out[node] = sc + hb2[0];
}

// ================= launch ==================================================
extern "C" void kernel_launch(void* const* d_in, const int* in_sizes, int n_in,
                              void* d_out, int out_size) {
    const float* x   = (const float*)d_in[0];
    const int* ei    = (const int*)d_in[1];     // int32 (JAX x64 disabled)
    const float* W1  = (const float*)d_in[2];
    const float* a1  = (const float*)d_in[3];
    const float* W2  = (const float*)d_in[4];
    const float* a2  = (const float*)d_in[5];
    const float* hw1 = (const float*)d_in[6];
    const float* hb1 = (const float*)d_in[7];
    const float* hw2 = (const float*)d_in[8];
    const float* hb2 = (const float*)d_in[9];
    float* out       = (float*)d_out;

    const int* src = ei;        // edge_index[0, :]
    const int* dst = ei + NE;   // edge_index[1, :]

    const int TB = 256;
    const int edgeBlocks = (NE + TB - 1) / TB;
    const int nodeBlocks = (NN + TB - 1) / TB;

    k_c12<<<1, 512>>>(W1, a1);
    k_pre<<<nodeBlocks, TB>>>(x);          // zero deg + ed1n table
    k_hist<<<edgeBlocks, TB>>>(dst);
    k_scan<<<1, 1024>>>();
    k_scatter<<<edgeBlocks, TB>>>(src, dst);
    k_permx<<<edgeBlocks, TB>>>(x);        // weights + premultiplied rows

    // layer 1 (streaming sum) + fused layer-2 projection
    k_gagg1_node2<<<(NN + 15) / 16, 512>>>(W1, W2, a2);

    // layer 2 gather + fused head
    k_gagg2_head<<<(NN + 7) / 8, TB>>>(hw1, hb1, hw2, hb2, out);
}

// round 17
// speedup vs baseline: 1.5563x; 1.5563x over previous
#include <cuda_runtime.h>
#include <cuda_bf16.h>
#include <math.h>

#define NN 50000
#define NE 800000
#define D1 128
#define D2 32

#define SCAN_T 1024
#define SCAN_B ((NN + SCAN_T - 1) / SCAN_T)   // 49

// ---------------- scratch (device globals; no allocations) ----------------
__device__ __align__(16) float g_Wh2[(size_t)NN * D2];
__device__ __align__(16) float g_xg[(size_t)NE * 8];  // premultiplied w*x rows
__device__ float g_w1[NE];           // layer-1 edge weights (CSR order)
__device__ float g_es2[NN], g_ed2[NN];
__device__ float g_ed1n[NN];         // x[n] . c2
__device__ int   g_deg[NN];          // histogram, then scatter cursor
__device__ int   g_rowstart[NN + 1];
__device__ int   g_bsum[SCAN_B];     // per-block scan totals
__device__ int   g_boff[SCAN_B];     // per-block exclusive offsets
__device__ int   g_csrc[NE];         // CSR: src node per slot (dst-sorted)
__device__ int   g_cdst[NE];         // CSR: dst node per slot
__device__ float g_c1[8], g_c2[8];   // W1 @ a1[:D1], W1 @ a1[D1:]

// ================= c1 = W1 @ a1[:D1], c2 = W1 @ a1[D1:] ===================
__global__ void k_c12(const float* __restrict__ W1,
                      const float* __restrict__ a1) {
    int w = threadIdx.x >> 5, lane = threadIdx.x & 31;  // 16 warps
    int k = w & 7;
    const float* av = a1 + ((w < 8) ? 0 : D1);
    float p = 0.f;
    for (int j = lane; j < D1; j += 32) p += W1[k * D1 + j] * av[j];
#pragma unroll
    for (int o = 16; o; o >>= 1) p += __shfl_xor_sync(0xffffffffu, p, o);
    if (lane == 0) {
        if (w < 8) g_c1[k] = p; else g_c2[k] = p;
    }
}

// ====== per-node pre-pass: zero deg + ed1n = x . c2 (after k_c12) =========
__global__ void k_pre(const float* __restrict__ x) {
    int i = blockIdx.x * blockDim.x + threadIdx.x;
    if (i >= NN) return;
    g_deg[i] = 0;
    const float4* xn = reinterpret_cast<const float4*>(x + (size_t)i * 8);
    float4 lo = xn[0], hi = xn[1];
    g_ed1n[i] = lo.x * g_c2[0] + lo.y * g_c2[1] + lo.z * g_c2[2] + lo.w * g_c2[3]
              + hi.x * g_c2[4] + hi.y * g_c2[5] + hi.z * g_c2[6] + hi.w * g_c2[7];
}

__global__ void k_hist(const int* __restrict__ dst) {
    int e = blockIdx.x * blockDim.x + threadIdx.x;
    if (e < NE) atomicAdd(&g_deg[dst[e]], 1);
}

// ========== hierarchical scan, phase 1: per-block exclusive scan ==========
__global__ void k_scan_local() {
    int t = threadIdx.x;
    int idx = blockIdx.x * SCAN_T + t;
    int v = (idx < NN) ? g_deg[idx] : 0;

    int lane = t & 31, w = t >> 5;
    int incl = v;
#pragma unroll
    for (int o = 1; o < 32; o <<= 1) {
        int u = __shfl_up_sync(0xffffffffu, incl, o);
        if (lane >= o) incl += u;
    }
    __shared__ int wsum[32];
    if (lane == 31) wsum[w] = incl;
    __syncthreads();
    if (w == 0) {
        int u = wsum[lane];
#pragma unroll
        for (int o = 1; o < 32; o <<= 1) {
            int q = __shfl_up_sync(0xffffffffu, u, o);
            if (lane >= o) u += q;
        }
        wsum[lane] = u;
    }
    __syncthreads();
    int excl = incl - v + ((w > 0) ? wsum[w - 1] : 0);

    if (idx < NN) g_rowstart[idx] = excl;          // block-local exclusive
    if (t == SCAN_T - 1) g_bsum[blockIdx.x] = excl + v;  // block total
}

// ========== phase 2: scan the 49 block totals (tiny, 1 block) =============
__global__ void k_scan_bsum() {
    __shared__ int s[64];
    int t = threadIdx.x;  // 64 threads
    int v = (t < SCAN_B) ? g_bsum[t] : 0;
    s[t] = v;
    __syncthreads();
#pragma unroll
    for (int o = 1; o < 64; o <<= 1) {
        int u = (t >= o) ? s[t - o] : 0;
        __syncthreads();
        s[t] += u;
        __syncthreads();
    }
    if (t < SCAN_B) g_boff[t] = s[t] - v;          // exclusive offset
    if (t == SCAN_B - 1) g_rowstart[NN] = s[t];    // grand total (= NE)
}

// ========== phase 3: add block offsets, zero deg (scatter cursor) =========
__global__ void k_scan_add() {
    int idx = blockIdx.x * blockDim.x + threadIdx.x;
    if (idx >= NN) return;
    g_rowstart[idx] += g_boff[idx >> 10];  // 1024 = SCAN_T per block
    g_deg[idx] = 0;
}

__global__ void k_scatter(const int* __restrict__ src,
                          const int* __restrict__ dst) {
    int e = blockIdx.x * blockDim.x + threadIdx.x;
    if (e >= NE) return;
    int d = dst[e];
    int pos = g_rowstart[d] + atomicAdd(&g_deg[d], 1);
    g_csrc[pos] = src[e];
    g_cdst[pos] = d;
}

// edge weight: exp(leaky_relu(logit)). Global max-shift dropped: it enters
// only through the +1e-9 denominator term (rel effect ~1e-10 here).
__device__ __forceinline__ float edge_w(float lg) {
    float v = (lg > 0.f) ? lg : 0.2f * lg;
    return __expf(v);
}

// ===== permute + full layer-1 edge math: xg[i] = w_i * x[csrc[i]] =========
__global__ void k_permx(const float* __restrict__ x) {
    int i = blockIdx.x * blockDim.x + threadIdx.x;
    if (i >= NE) return;
    int s = g_csrc[i];
    int d = g_cdst[i];
    const float4* xs = reinterpret_cast<const float4*>(x + (size_t)s * 8);
    float4 lo = xs[0], hi = xs[1];
    float es = lo.x * g_c1[0] + lo.y * g_c1[1] + lo.z * g_c1[2] + lo.w * g_c1[3]
             + hi.x * g_c1[4] + hi.y * g_c1[5] + hi.z * g_c1[6] + hi.w * g_c1[7];
    float w = edge_w(es + g_ed1n[d]);
    g_w1[i] = w;
    lo.x *= w; lo.y *= w; lo.z *= w; lo.w *= w;
    hi.x *= w; hi.y *= w; hi.z *= w; hi.w *= w;
    float4* o = reinterpret_cast<float4*>(g_xg) + (size_t)i * 2;
    o[0] = lo; o[1] = hi;
}

// ===== fused layer1: pure streaming sum + @W1 + elu + node2 matvec ========
__global__ void k_gagg1_node2(const float* __restrict__ W1,
                              const float* __restrict__ W2,
                              const float* __restrict__ a2) {
    __shared__ float sW1[8 * D1];    // 4 KB
    __shared__ float sW2[D1 * D2];   // 16 KB
    __shared__ float sa[2 * D2];
    __shared__ float sh[16][D1];     // per-warp out1 row (16 warps)
    int tid = threadIdx.x;
    for (int i = tid; i < 8 * D1; i += blockDim.x) sW1[i] = W1[i];
    for (int i = tid; i < D1 * D2; i += blockDim.x) sW2[i] = W2[i];
    for (int i = tid; i < 2 * D2; i += blockDim.x) sa[i] = a2[i];
    __syncthreads();

    int warp = tid >> 5, lane = tid & 31;
    int node = blockIdx.x * (blockDim.x >> 5) + warp;
    if (node >= NN) return;

    int beg = g_rowstart[node], end = g_rowstart[node + 1];
    int half = lane & 1;  // lane pair per edge: even=comps 0-3, odd=4-7

    // streaming sum of premultiplied rows (16 edges / 512B per pass)
    float a0 = 0.f, a1r = 0.f, a2r = 0.f, a3 = 0.f;
    for (int idx = beg + (lane >> 1); idx < end; idx += 16) {
        float4 v = reinterpret_cast<const float4*>(g_xg)[(size_t)idx * 2 + half];
        a0 += v.x; a1r += v.y; a2r += v.z; a3 += v.w;
    }
    // streaming weight sum (coalesced, all 32 lanes)
    float psum = 0.f;
    for (int i = beg + lane; i < end; i += 32) psum += g_w1[i];

    // reduce over lane pairs; even lanes hold comps 0-3, odd hold 4-7
#pragma unroll
    for (int o = 2; o <= 16; o <<= 1) {
        a0  += __shfl_xor_sync(0xffffffffu, a0,  o);
        a1r += __shfl_xor_sync(0xffffffffu, a1r, o);
        a2r += __shfl_xor_sync(0xffffffffu, a2r, o);
        a3  += __shfl_xor_sync(0xffffffffu, a3,  o);
    }
#pragma unroll
    for (int o = 16; o; o >>= 1) psum += __shfl_xor_sync(0xffffffffu, psum, o);

    // exchange halves so every lane holds the full aggx[8]
    float t0 = __shfl_xor_sync(0xffffffffu, a0,  1);
    float t1 = __shfl_xor_sync(0xffffffffu, a1r, 1);
    float t2 = __shfl_xor_sync(0xffffffffu, a2r, 1);
    float t3 = __shfl_xor_sync(0xffffffffu, a3,  1);
    float b0 = half ? t0 : a0,  b4 = half ? a0  : t0;
    float b1 = half ? t1 : a1r, b5 = half ? a1r : t1;
    float b2 = half ? t2 : a2r, b6 = half ? a2r : t2;
    float b3 = half ? t3 : a3,  b7 = half ? a3  : t3;

    float inv = 1.f / (psum + 1e-9f);
    // out1[j] = elu( inv * (aggx @ W1)[j] )
#pragma unroll
    for (int i = 0; i < 4; i++) {
        int j = i * 32 + lane;
        float o = b0 * sW1[0 * D1 + j] + b1 * sW1[1 * D1 + j]
                + b2 * sW1[2 * D1 + j] + b3 * sW1[3 * D1 + j]
                + b4 * sW1[4 * D1 + j] + b5 * sW1[5 * D1 + j]
                + b6 * sW1[6 * D1 + j] + b7 * sW1[7 * D1 + j];
        o *= inv;
        o = (o > 0.f) ? o : expm1f(o);  // elu fused
        sh[warp][j] = o;
    }
    __syncwarp();

    // node2: Wh2 = out1 @ W2, es2/ed2
    int j = lane;
    float acc = 0.f;
#pragma unroll 8
    for (int k = 0; k < D1; k++) acc += sh[warp][k] * sW2[k * D2 + j];

    g_Wh2[(size_t)node * D2 + j] = acc;

    float es = acc * sa[j];
    float ed = acc * sa[D2 + j];
#pragma unroll
    for (int o = 16; o; o >>= 1) {
        es += __shfl_down_sync(0xffffffffu, es, o);
        ed += __shfl_down_sync(0xffffffffu, ed, o);
    }
    if (lane == 0) {
        g_es2[node] = es;
        g_ed2[node] = ed;
    }
}

// ====== fused: chunked gather layer2 (D=32) + elu + MLP head ==============
__global__ void k_gagg2_head(const float* __restrict__ hw1,
                             const float* __restrict__ hb1,
                             const float* __restrict__ hw2,
                             const float* __restrict__ hb2,
                             float* __restrict__ out) {
    __shared__ float sw1[32 * 32];
    __shared__ float sb1[32];
    __shared__ float sw2[32];
    __shared__ float sh[8][32];
    int tid = threadIdx.x;
    for (int i = tid; i < 32 * 32; i += blockDim.x) sw1[i] = hw1[i];
    if (tid < 32) { sb1[tid] = hb1[tid]; sw2[tid] = hw2[tid]; }
    __syncthreads();

    int warp = tid >> 5, lane = tid & 31;
    int node = blockIdx.x * (blockDim.x >> 5) + warp;
    if (node >= NN) return;

    int beg = g_rowstart[node], end = g_rowstart[node + 1];
    float edc = g_ed2[node];

    float acc = 0.f, psum = 0.f;
    for (int base = beg; base < end; base += 32) {
        int cnt = min(32, end - base);
        int   s = 0;
        float w = 0.f;
        if (lane < cnt) {
            s = g_csrc[base + lane];
            w = edge_w(g_es2[s] + edc);
        }
        psum += w;
        if (cnt == 32) {
#pragma unroll 8
            for (int j = 0; j < 32; j++) {
                int   sj = __shfl_sync(0xffffffffu, s, j);
                float wj = __shfl_sync(0xffffffffu, w, j);
                acc += wj * g_Wh2[(size_t)sj * D2 + lane];
            }
        } else {
            for (int j = 0; j < cnt; j++) {
                int   sj = __shfl_sync(0xffffffffu, s, j);
                float wj = __shfl_sync(0xffffffffu, w, j);
                acc += wj * g_Wh2[(size_t)sj * D2 + lane];
            }
        }
    }
    float asum = psum;
#pragma unroll
    for (int o = 16; o; o >>= 1) asum += __shfl_xor_sync(0xffffffffu, asum, o);

    acc *= 1.f / (asum + 1e-9f);
    float h = (acc > 0.f) ? acc : expm1f(acc);   // elu fused

    sh[warp][lane] = h;
    __syncwarp();

    float z = sb1[lane];
#pragma unroll 8
    for (int k = 0; k < 32; k++) z += sh[warp][k] * sw1[k * 32 + lane];

    // exact gelu: 0.5*x*(1+erf(x/sqrt(2)))
    float g = 0.5f * z * (1.f + erff(z * 0.70710678118654752f));
    float sc = g * sw2[lane];
#pragma unroll
    for (int o = 16; o; o >>= 1) sc += __shfl_down_sync(0xffffffffu, sc, o);
    if (lane == 0) out[node] = sc + hb2[0];
}

// ================= launch ==================================================
extern "C" void kernel_launch(void* const* d_in, const int* in_sizes, int n_in,
                              void* d_out, int out_size) {
    const float* x   = (const float*)d_in[0];
    const int* ei    = (const int*)d_in[1];     // int32 (JAX x64 disabled)
    const float* W1  = (const float*)d_in[2];
    const float* a1  = (const float*)d_in[3];
    const float* W2  = (const float*)d_in[4];
    const float* a2  = (const float*)d_in[5];
    const float* hw1 = (const float*)d_in[6];
    const float* hb1 = (const float*)d_in[7];
    const float* hw2 = (const float*)d_in[8];
    const float* hb2 = (const float*)d_in[9];
    float* out       = (float*)d_out;

    const int* src = ei;        // edge_index[0, :]
    const int* dst = ei + NE;   // edge_index[1, :]

    const int TB = 256;
    const int edgeBlocks = (NE + TB - 1) / TB;
    const int nodeBlocks = (NN + TB - 1) / TB;

    k_c12<<<1, 512>>>(W1, a1);
    k_pre<<<nodeBlocks, TB>>>(x);            // zero deg + ed1n table
    k_hist<<<edgeBlocks, TB>>>(dst);
    k_scan_local<<<SCAN_B, SCAN_T>>>();      // parallel hierarchical scan
    k_scan_bsum<<<1, 64>>>();
    k_scan_add<<<nodeBlocks, TB>>>();
    k_scatter<<<edgeBlocks, TB>>>(src, dst);
    k_permx<<<edgeBlocks, TB>>>(x);          // weights + premultiplied rows

    // layer 1 (streaming sum) + fused layer-2 projection
    k_gagg1_node2<<<(NN + 15) / 16, 512>>>(W1, W2, a2);

    // layer 2 gather + fused head
    k_gagg2_head<<<(NN + 7) / 8, TB>>>(hw1, hb1, hw2, hb2, out);
}